// round 7
// baseline (speedup 1.0000x reference)
#include <cuda_runtime.h>
#include <cuda_bf16.h>

// ST-BIF multi-step neuron, T=4 timesteps.
//   x: [T*B, L, D] fp32 viewed as [T, B*L*D]; per neuron:
//     v = 0.5*vth; tc = 0
//     per step: H = v + x_t
//       spike = +1 if (H >= vth && tc < 15)
//               -1 else if (H < 0 && tc > 0)
//                0 otherwise
//       v = H - spike*vth; tc += spike; out_t = spike*vth
// Memory-bound: 192 MiB in + 192 MiB out.

#define POS_MAX 15.0f
#define NEG_MIN 0.0f
#define TSTEPS  4

__device__ __forceinline__ float bif_step(float& v, float& tc, float xv, float vth) {
    float H = v + xv;
    float spike;
    if (H >= vth && tc < POS_MAX)      spike = 1.0f;
    else if (H < 0.0f && tc > NEG_MIN) spike = -1.0f;
    else                               spike = 0.0f;
    v  = H - spike * vth;
    tc = tc + spike;
    return spike * vth;
}

__global__ void __launch_bounds__(256)
st_bif_ms_kernel(const float* __restrict__ x,
                 const float* __restrict__ qth_ptr,
                 float* __restrict__ out,
                 int stepN)  // elements per timestep (B*L*D)
{
    int idx = (blockIdx.x * blockDim.x + threadIdx.x) * 4;
    if (idx >= stepN) return;

    const float vth = __ldg(qth_ptr);

    // Front-batch all 4 timestep loads: 4 independent LDG.128 -> MLP=4
    float4 xs0 = *reinterpret_cast<const float4*>(x + idx);
    float4 xs1 = *reinterpret_cast<const float4*>(x + idx + (size_t)stepN);
    float4 xs2 = *reinterpret_cast<const float4*>(x + idx + (size_t)2 * stepN);
    float4 xs3 = *reinterpret_cast<const float4*>(x + idx + (size_t)3 * stepN);

    float xv[TSTEPS][4] = {
        {xs0.x, xs0.y, xs0.z, xs0.w},
        {xs1.x, xs1.y, xs1.z, xs1.w},
        {xs2.x, xs2.y, xs2.z, xs2.w},
        {xs3.x, xs3.y, xs3.z, xs3.w},
    };

    float v[4], tc[4];
    #pragma unroll
    for (int j = 0; j < 4; j++) { v[j] = 0.5f * vth; tc[j] = 0.0f; }

    float o[TSTEPS][4];
    #pragma unroll
    for (int t = 0; t < TSTEPS; t++) {
        #pragma unroll
        for (int j = 0; j < 4; j++) {
            o[t][j] = bif_step(v[j], tc[j], xv[t][j], vth);
        }
    }

    *reinterpret_cast<float4*>(out + idx)                      = make_float4(o[0][0], o[0][1], o[0][2], o[0][3]);
    *reinterpret_cast<float4*>(out + idx + (size_t)stepN)      = make_float4(o[1][0], o[1][1], o[1][2], o[1][3]);
    *reinterpret_cast<float4*>(out + idx + (size_t)2 * stepN)  = make_float4(o[2][0], o[2][1], o[2][2], o[2][3]);
    *reinterpret_cast<float4*>(out + idx + (size_t)3 * stepN)  = make_float4(o[3][0], o[3][1], o[3][2], o[3][3]);
}

extern "C" void kernel_launch(void* const* d_in, const int* in_sizes, int n_in,
                              void* d_out, int out_size) {
    const float* x   = (const float*)d_in[0];   // [T*B, L, D] fp32
    const float* qth = (const float*)d_in[1];   // scalar fp32
    float* out = (float*)d_out;

    int total = in_sizes[0];         // T*B*L*D = 50,331,648
    int stepN = total / TSTEPS;      // B*L*D   = 12,582,912 (divisible by 4)

    int threads = stepN / 4;         // one thread per float4
    int tpb = 256;
    int blocks = (threads + tpb - 1) / tpb;
    st_bif_ms_kernel<<<blocks, tpb>>>(x, qth, out, stepN);
}